// round 6
// baseline (speedup 1.0000x reference)
#include <cuda_runtime.h>

// AverageSpanExtractor: out[b,n,:] = mean(seq[b, start:end, :]) * mask[b,n]
// seq:   [B,S,D] float32   (d_in[0])
// spans: [B,N,2] int32     (d_in[1])  (start, exclusive end)
// mask:  [B,N]   int32     (d_in[2])
// out:   [B,N,D] float32
//
// CTA per span (8192 CTAs, 128 threads); thread t owns float4 column t of
// every row, so the block walks one linear cnt*2KB chunk fully coalesced.
// unroll 8 keeps 8 float4 loads (512B) in flight per thread -> ~20KB/SM
// bytes-in-flight at 10 CTAs/SM, which is the lever for gather bandwidth.

#define MAX_W 20

__global__ __launch_bounds__(128, 10)
void avg_span_kernel(const float* __restrict__ seq,
                     const int* __restrict__ spans,
                     const int* __restrict__ mask,
                     float* __restrict__ out,
                     int S, int D, int N)
{
    const int n = blockIdx.x;           // span index
    const int b = blockIdx.y;           // batch index
    const int t = threadIdx.x;          // 0..127, owns float4 column t

    const int sp = b * N + n;
    const int start = spans[2 * sp];
    const int end_e = spans[2 * sp + 1];        // exclusive end
    int cnt = end_e - start;                    // width in [1, 20]
    cnt = (cnt < MAX_W) ? cnt : MAX_W;          // reference's static clamp
    cnt = (cnt > 0) ? cnt : 1;

    const int d4 = D >> 2;                      // 128 float4 per row
    const float4* __restrict__ p =
        (const float4*)(seq + (long long)b * S * D) + (long long)start * d4 + t;

    float4 acc = make_float4(0.f, 0.f, 0.f, 0.f);

    // wide load window: 8 independent float4 loads in flight per thread
    #pragma unroll 8
    for (int i = 0; i < cnt; ++i) {
        float4 v = *p;
        p += d4;
        acc.x += v.x; acc.y += v.y; acc.z += v.z; acc.w += v.w;
    }

    const float scale = (float)mask[sp] / (float)cnt;
    acc.x *= scale; acc.y *= scale; acc.z *= scale; acc.w *= scale;

    float4* out4 = (float4*)(out + (long long)sp * D);
    out4[t] = acc;
}

extern "C" void kernel_launch(void* const* d_in, const int* in_sizes, int n_in,
                              void* d_out, int out_size)
{
    const float* seq  = (const float*)d_in[0];
    const int* spans  = (const int*)d_in[1];
    const int* mask   = (const int*)d_in[2];
    float* out        = (float*)d_out;

    const int D = 512;
    const int S = 2048;
    const int B = in_sizes[0] / (S * D);         // 8
    const int N = in_sizes[2] / B;               // 1024

    dim3 grid(N, B);
    dim3 block(D / 4);                           // 128 threads
    avg_span_kernel<<<grid, block>>>(seq, spans, mask, out, S, D, N);
}